// round 15
// baseline (speedup 1.0000x reference)
#include <cuda_runtime.h>
#include <cstdint>

#define B_  32
#define C_  256
#define H_  64
#define W_  64
#define HW_ 4096
#define EPS 1e-5f

// ---------------- scratch (device globals: no allocations allowed) ----------
__device__ float g_edge[(size_t)B_ * C_ * HW_];   // relu(bn(dwconv(x))), tf32-rounded
__device__ float g_t1 [(size_t)B_ * C_ * HW_];    // bn1(fusion conv)
__device__ float g_t2 [(size_t)B_ * C_ * HW_];    // deform dwconv out (tf32-rounded)
__device__ float g_avg[B_ * C_];
__device__ float g_att[B_ * C_];
__device__ float g_wt1[C_ * 2 * C_];              // tf32-rounded fusion_w
__device__ float g_wt2[C_ * C_];                  // tf32-rounded balance_w

__device__ __forceinline__ uint32_t f2tf32(float x) {
    uint32_t r;
    asm("cvt.rna.tf32.f32 %0, %1;" : "=r"(r) : "f"(x));
    return r;
}

// ---------------- 0) weight pre-round to tf32 -------------------------------
__global__ __launch_bounds__(256) void wcvt_kernel(const float* __restrict__ w1,
                                                   const float* __restrict__ w2) {
    int i = blockIdx.x * 256 + threadIdx.x;
    if (i < C_ * 2 * C_) g_wt1[i] = __uint_as_float(f2tf32(w1[i]));
    if (i < C_ * C_)     g_wt2[i] = __uint_as_float(f2tf32(w2[i]));
}

// ---------------- 2) SE MLP -------------------------------------------------
__global__ __launch_bounds__(512) void se_kernel(const float* __restrict__ fc1_w,
                                                 const float* __restrict__ fc2_w) {
    __shared__ float sa[B_ * C_];
    __shared__ float shh[B_ * 16];
    int tid = threadIdx.x;
    for (int i = tid; i < B_ * C_; i += 512) sa[i] = g_avg[i];
    __syncthreads();
    {
        int b = tid >> 4, j = tid & 15;
        float s = 0.f;
        #pragma unroll 8
        for (int c = 0; c < C_; c++) s += sa[b * C_ + c] * fc1_w[j * C_ + c];
        shh[b * 16 + j] = fmaxf(s, 0.f);
    }
    __syncthreads();
    for (int idx = tid; idx < B_ * C_; idx += 512) {
        int b = idx >> 8, o = idx & 255;
        float s = 0.f;
        #pragma unroll
        for (int j = 0; j < 16; j++) s += shh[b * 16 + j] * fc2_w[o * 16 + j];
        g_att[idx] = 1.0f / (1.0f + expf(-s));
    }
}

// ------- 3/5) depthwise 3x3, 4 cols x 4 rows per thread, float4 path --------
template<bool BNRELU, bool DOMEAN, bool ROUND>
__global__ __launch_bounds__(256) void dwconv_kernel(const float* __restrict__ src,
                                                     const float* __restrict__ w9,
                                                     float* __restrict__ dst,
                                                     const float* __restrict__ gma,
                                                     const float* __restrict__ bta,
                                                     const float* __restrict__ mn,
                                                     const float* __restrict__ vr) {
    __shared__ float sh[66][68];      // phys col p = image col p-1; row r = image row r-1
    __shared__ float ws[8];
    int plane = blockIdx.x;
    int c = plane & (C_ - 1);
    const float* sp = src + (size_t)plane * HW_;
    int tid = threadIdx.x;

    // interior fill: image rows 0..63 -> phys rows 1..64, 16 float4 per row
    #pragma unroll
    for (int v = tid; v < 1024; v += 256) {
        int r = v >> 4, q = (v & 15) << 2;
        float4 val = *(const float4*)(sp + r * W_ + q);
        sh[r + 1][q + 1] = val.x;
        sh[r + 1][q + 2] = val.y;
        sh[r + 1][q + 3] = val.z;
        sh[r + 1][q + 4] = val.w;
    }
    // border zeros: rows 0 & 65 (cols 0..65); cols 0 & 65 (rows 1..64)
    if (tid < 132) {
        int cc = tid % 66, rr = (tid / 66) * 65;
        sh[rr][cc] = 0.f;
    } else if (tid < 196) {
        int i = tid - 132;            // 0..63 -> rows 1..64, both col borders
        sh[1 + i][0]  = 0.f;
        sh[1 + i][65] = 0.f;
    }

    float w[9];
    #pragma unroll
    for (int i = 0; i < 9; i++) w[i] = w9[c * 9 + i];
    float inv = 1.f, add = 0.f;
    if (BNRELU) { inv = gma[c] * rsqrtf(vr[c] + EPS); add = bta[c] - mn[c] * inv; }
    __syncthreads();

    const int c0 = (tid & 15) * 4;    // output cols c0..c0+3 (phys c0..c0+5)
    const int r0 = (tid >> 4) * 4;    // output rows r0..r0+3
    float* dp = dst + (size_t)plane * HW_;

    float4 t4 = *(const float4*)&sh[r0][c0];
    float2 t2 = *(const float2*)&sh[r0][c0 + 4];
    float4 m4 = *(const float4*)&sh[r0 + 1][c0];
    float2 m2 = *(const float2*)&sh[r0 + 1][c0 + 4];
    float msum = 0.f;
    #pragma unroll
    for (int i = 0; i < 4; i++) {
        float4 b4 = *(const float4*)&sh[r0 + 2 + i][c0];
        float2 b2 = *(const float2*)&sh[r0 + 2 + i][c0 + 4];
        float s0 = w[0]*t4.x + w[1]*t4.y + w[2]*t4.z
                 + w[3]*m4.x + w[4]*m4.y + w[5]*m4.z
                 + w[6]*b4.x + w[7]*b4.y + w[8]*b4.z;
        float s1 = w[0]*t4.y + w[1]*t4.z + w[2]*t4.w
                 + w[3]*m4.y + w[4]*m4.z + w[5]*m4.w
                 + w[6]*b4.y + w[7]*b4.z + w[8]*b4.w;
        float s2 = w[0]*t4.z + w[1]*t4.w + w[2]*t2.x
                 + w[3]*m4.z + w[4]*m4.w + w[5]*m2.x
                 + w[6]*b4.z + w[7]*b4.w + w[8]*b2.x;
        float s3 = w[0]*t4.w + w[1]*t2.x + w[2]*t2.y
                 + w[3]*m4.w + w[4]*m2.x + w[5]*m2.y
                 + w[6]*b4.w + w[7]*b2.x + w[8]*b2.y;
        if (DOMEAN) msum += m4.y + m4.z + m4.w + m2.x;   // x[r0+i][c0..c0+3]
        if (BNRELU) {
            s0 = fmaxf(s0 * inv + add, 0.f);
            s1 = fmaxf(s1 * inv + add, 0.f);
            s2 = fmaxf(s2 * inv + add, 0.f);
            s3 = fmaxf(s3 * inv + add, 0.f);
        }
        if (ROUND) {
            s0 = __uint_as_float(f2tf32(s0));
            s1 = __uint_as_float(f2tf32(s1));
            s2 = __uint_as_float(f2tf32(s2));
            s3 = __uint_as_float(f2tf32(s3));
        }
        float4 outv = make_float4(s0, s1, s2, s3);
        *(float4*)&dp[(r0 + i) * W_ + c0] = outv;
        t4 = m4; t2 = m2;
        m4 = b4; m2 = b2;
    }

    if (DOMEAN) {
        #pragma unroll
        for (int o = 16; o; o >>= 1) msum += __shfl_xor_sync(0xffffffffu, msum, o);
        if ((tid & 31) == 0) ws[tid >> 5] = msum;
        __syncthreads();
        if (tid == 0) {
            float t = 0.f;
            #pragma unroll
            for (int i = 0; i < 8; i++) t += ws[i];
            g_avg[plane] = t * (1.0f / HW_);
        }
    }
}

// ========= tf32 mma.sync GEMM, K32 chunks, 3-stage cp.async + ldmatrix ======
__device__ __forceinline__ uint32_t smem_u32(const void* p) {
    uint32_t a;
    asm("{ .reg .u64 t; cvta.to.shared.u64 t, %1; cvt.u32.u64 %0, t; }"
        : "=r"(a) : "l"(p));
    return a;
}
__device__ __forceinline__ void mma_tf32_16x8x8(
    float& d0, float& d1, float& d2, float& d3,
    uint32_t a0, uint32_t a1, uint32_t a2, uint32_t a3,
    uint32_t b0, uint32_t b1) {
    asm volatile(
        "mma.sync.aligned.m16n8k8.row.col.f32.tf32.tf32.f32 "
        "{%0,%1,%2,%3}, {%4,%5,%6,%7}, {%8,%9}, {%0,%1,%2,%3};"
        : "+f"(d0), "+f"(d1), "+f"(d2), "+f"(d3)
        : "r"(a0), "r"(a1), "r"(a2), "r"(a3), "r"(b0), "r"(b1));
}
__device__ __forceinline__ void ldsm_x4(uint32_t& r0, uint32_t& r1,
                                        uint32_t& r2, uint32_t& r3, uint32_t a) {
    asm volatile("ldmatrix.sync.aligned.m8n8.x4.shared.b16 {%0,%1,%2,%3}, [%4];"
                 : "=r"(r0), "=r"(r1), "=r"(r2), "=r"(r3) : "r"(a));
}
#define CP16(dst, src) \
    asm volatile("cp.async.cg.shared.global [%0], [%1], 16;" :: "r"(dst), "l"(src))
#define CP_COMMIT() asm volatile("cp.async.commit_group;" ::: "memory")
#define CP_WAIT1()  asm volatile("cp.async.wait_group 1;" ::: "memory")

// Block tile: M=128 channels x N=128 pixels, K chunk 32, 8 warps (2M x 4N).
// A smem rows [m][36] floats; B smem rows [k][136] floats; 3 stages; 2 CTA/SM.
// G1 chunks with k < C_ apply SE scale + tf32 cvt at fragment load; chunks in
// the edge half (and all of G2) are pure LDS (sources pre-rounded to tf32).
template<int KTOT, bool IS_G1>
__global__ __launch_bounds__(256, 2) void tgemm_kernel(
    const float* __restrict__ act,
    const float* __restrict__ wgt,    // pre-rounded tf32 weights
    const float* __restrict__ bias,
    const float* __restrict__ gma, const float* __restrict__ bta,
    const float* __restrict__ mnn, const float* __restrict__ vr,
    const float* __restrict__ xg,
    float* __restrict__ dst)
{
    extern __shared__ char smem[];
    constexpr int AROW = 36;                 // floats per A row (32 + pad)
    constexpr int BROW = 136;                // floats per B row (128 + pad)
    constexpr int ASTG = 128 * AROW * 4;     // 18432 B per stage
    constexpr int BSTG = 32 * BROW * 4;      // 17408 B per stage
    constexpr int AOFF = KTOT * 4;           // att table first
    constexpr int BOFF = AOFF + 3 * ASTG;
    const uint32_t sb = smem_u32(smem);
    float* att_s = (float*)smem;

    const int tid = threadIdx.x;
    const int wid = tid >> 5, lane = tid & 31;
    const int g = lane >> 2, tig = lane & 3;
    const int b  = blockIdx.z;
    const int o0 = blockIdx.y * 128;
    const int p0 = blockIdx.x * 128;
    const int warpM = (wid & 1) * 64;
    const int warpN = (wid >> 1) * 32;

    const float* actb = act    + (size_t)b * C_ * HW_;
    const float* edgb = g_edge + (size_t)b * C_ * HW_;

    if (IS_G1) {
        const float* attb = g_att + b * C_;
        for (int i = tid; i < C_; i += 256) att_s[i] = attb[i];
    }

    // ldmatrix per-lane row offset within an A stage
    const int lrow = (lane & 7) + ((lane >> 3) & 1) * 8;
    const int lk   = (lane >> 4) * 4;
    const uint32_t a_lane_off = (uint32_t)((warpM + lrow) * AROW + lk) * 4;

    #define ISSUE_CHUNK(T)                                                        \
    {                                                                             \
        const int slot_ = (T) % 3;                                                \
        const int k0_ = (T) * 32;                                                 \
        const uint32_t ab_ = sb + AOFF + slot_ * ASTG;                            \
        const uint32_t bb_ = sb + BOFF + slot_ * BSTG;                            \
        _Pragma("unroll")                                                         \
        for (int i = 0; i < 4; i++) {                                             \
            const int ai_ = tid + i * 256;                                        \
            const int am_ = ai_ >> 3, aq_ = ai_ & 7;                              \
            const float* as_ = wgt + (size_t)(o0 + am_) * KTOT + k0_ + aq_ * 4;   \
            CP16(ab_ + (uint32_t)(am_ * AROW + aq_ * 4) * 4, as_);                \
            const int bkr_ = ai_ >> 5, bcq_ = ai_ & 31;                           \
            const int kg_ = k0_ + bkr_;                                           \
            const float* bs_;                                                     \
            if (IS_G1 && kg_ >= C_)                                               \
                bs_ = edgb + (size_t)(kg_ - C_) * HW_ + p0 + bcq_ * 4;            \
            else                                                                  \
                bs_ = actb + (size_t)kg_ * HW_ + p0 + bcq_ * 4;                   \
            CP16(bb_ + (uint32_t)(bkr_ * BROW + bcq_ * 4) * 4, bs_);              \
        }                                                                         \
    }

    float acc[4][4][4];
    #pragma unroll
    for (int i = 0; i < 4; i++)
        #pragma unroll
        for (int j = 0; j < 4; j++)
            #pragma unroll
            for (int q = 0; q < 4; q++) acc[i][j][q] = 0.f;

    const int NT = KTOT / 32;
    ISSUE_CHUNK(0); CP_COMMIT();
    ISSUE_CHUNK(1); CP_COMMIT();

    for (int t = 0; t < NT; t++) {
        CP_WAIT1();
        __syncthreads();
        if (t + 2 < NT) ISSUE_CHUNK(t + 2);
        CP_COMMIT();

        const int slot = t % 3;
        const uint32_t Aad = sb + AOFF + slot * ASTG + a_lane_off;
        const float* Br = (const float*)(smem + BOFF + slot * BSTG);
        const int kb0 = t * 32;
        const bool sc = IS_G1 && (kb0 < C_);   // uniform per chunk

        #pragma unroll
        for (int kb = 0; kb < 32; kb += 8) {
            uint32_t af[4][4], bf[4][2];
            #pragma unroll
            for (int mt = 0; mt < 4; mt++)
                ldsm_x4(af[mt][0], af[mt][1], af[mt][2], af[mt][3],
                        Aad + (uint32_t)(mt * 16 * AROW + kb) * 4);
            if (sc) {
                const float sa0 = att_s[kb0 + kb + tig];
                const float sa1 = att_s[kb0 + kb + tig + 4];
                #pragma unroll
                for (int nt = 0; nt < 4; nt++) {
                    const int n = warpN + nt * 8 + g;
                    bf[nt][0] = f2tf32(Br[(kb + tig) * BROW + n] * sa0);
                    bf[nt][1] = f2tf32(Br[(kb + tig + 4) * BROW + n] * sa1);
                }
            } else {
                #pragma unroll
                for (int nt = 0; nt < 4; nt++) {
                    const int n = warpN + nt * 8 + g;
                    bf[nt][0] = __float_as_uint(Br[(kb + tig) * BROW + n]);
                    bf[nt][1] = __float_as_uint(Br[(kb + tig + 4) * BROW + n]);
                }
            }
            #pragma unroll
            for (int mt = 0; mt < 4; mt++)
                #pragma unroll
                for (int nt = 0; nt < 4; nt++)
                    mma_tf32_16x8x8(acc[mt][nt][0], acc[mt][nt][1],
                                    acc[mt][nt][2], acc[mt][nt][3],
                                    af[mt][0], af[mt][1], af[mt][2], af[mt][3],
                                    bf[nt][0], bf[nt][1]);
        }
    }
    #undef ISSUE_CHUNK

    // ---- epilogue: BN(+bias)(+gate) and store ----
    const size_t bb = (size_t)b * C_ * HW_;
    #pragma unroll
    for (int mt = 0; mt < 4; mt++) {
        const int olo = o0 + warpM + mt * 16 + g;
        const int ohi = olo + 8;
        const float invlo = gma[olo] * rsqrtf(vr[olo] + EPS);
        const float addlo = bta[olo] - mnn[olo] * invlo + bias[olo] * invlo;
        const float invhi = gma[ohi] * rsqrtf(vr[ohi] + EPS);
        const float addhi = bta[ohi] - mnn[ohi] * invhi + bias[ohi] * invhi;
        #pragma unroll
        for (int nt = 0; nt < 4; nt++) {
            const int n = p0 + warpN + nt * 8 + 2 * tig;
            const size_t lo = bb + (size_t)olo * HW_ + n;
            const size_t hi = bb + (size_t)ohi * HW_ + n;
            float2 vlo, vhi;
            vlo.x = acc[mt][nt][0] * invlo + addlo;
            vlo.y = acc[mt][nt][1] * invlo + addlo;
            vhi.x = acc[mt][nt][2] * invhi + addhi;
            vhi.y = acc[mt][nt][3] * invhi + addhi;
            if (!IS_G1) {
                float2 xlo = *(const float2*)(xg + lo);
                float2 xhi = *(const float2*)(xg + hi);
                vlo.x *= xlo.x; vlo.y *= xlo.y;
                vhi.x *= xhi.x; vhi.y *= xhi.y;
            }
            *(float2*)(dst + lo) = vlo;
            *(float2*)(dst + hi) = vhi;
        }
    }
}

// ---------------- launch ----------------------------------------------------
extern "C" void kernel_launch(void* const* d_in, const int* in_sizes, int n_in,
                              void* d_out, int out_size) {
    const float* x          = (const float*)d_in[0];
    const float* edge_w     = (const float*)d_in[1];
    const float* edge_gamma = (const float*)d_in[2];
    const float* edge_beta  = (const float*)d_in[3];
    const float* edge_mean  = (const float*)d_in[4];
    const float* edge_var   = (const float*)d_in[5];
    const float* fc1_w      = (const float*)d_in[6];
    const float* fc2_w      = (const float*)d_in[7];
    const float* fusion_w   = (const float*)d_in[8];
    const float* fusion_b   = (const float*)d_in[9];
    const float* bn1_gamma  = (const float*)d_in[10];
    const float* bn1_beta   = (const float*)d_in[11];
    const float* bn1_mean   = (const float*)d_in[12];
    const float* bn1_var    = (const float*)d_in[13];
    const float* deform_w   = (const float*)d_in[14];
    const float* balance_w  = (const float*)d_in[15];
    const float* balance_b  = (const float*)d_in[16];
    const float* bn2_gamma  = (const float*)d_in[17];
    const float* bn2_beta   = (const float*)d_in[18];
    const float* bn2_mean   = (const float*)d_in[19];
    const float* bn2_var    = (const float*)d_in[20];
    float* out = (float*)d_out;

    float *pe = nullptr, *pt1 = nullptr, *pt2 = nullptr, *pw1 = nullptr, *pw2 = nullptr;
    cudaGetSymbolAddress((void**)&pe,  g_edge);
    cudaGetSymbolAddress((void**)&pt1, g_t1);
    cudaGetSymbolAddress((void**)&pt2, g_t2);
    cudaGetSymbolAddress((void**)&pw1, g_wt1);
    cudaGetSymbolAddress((void**)&pw2, g_wt2);

    // smem: att(KTOT*4) + 3*ASTG(18432) + 3*BSTG(17408)
    const int SMEM_G1 = 512 * 4 + 3 * 18432 + 3 * 17408;  // 109568
    const int SMEM_G2 = 256 * 4 + 3 * 18432 + 3 * 17408;  // 108544
    cudaFuncSetAttribute(tgemm_kernel<512, true>,
                         cudaFuncAttributeMaxDynamicSharedMemorySize, SMEM_G1);
    cudaFuncSetAttribute(tgemm_kernel<256, false>,
                         cudaFuncAttributeMaxDynamicSharedMemorySize, SMEM_G2);

    const int nplanes = B_ * C_;

    // 0) pre-round weights to tf32
    wcvt_kernel<<<(C_ * 2 * C_ + 255) / 256, 256>>>(fusion_w, balance_w);
    // 1+3) edge dwconv + BN + ReLU (tf32-rounded) -> g_edge, fused mean -> g_avg
    dwconv_kernel<true, true, true><<<nplanes, 256>>>(x, edge_w, pe,
                                                      edge_gamma, edge_beta,
                                                      edge_mean, edge_var);
    // 2) SE MLP -> g_att
    se_kernel<<<1, 512>>>(fc1_w, fc2_w);
    // 4) fusion 1x1 conv (tf32 mma.sync, K32, 3-stage, 2 CTA/SM) -> g_t1
    dim3 grid(HW_ / 128, C_ / 128, B_);
    tgemm_kernel<512, true><<<grid, 256, SMEM_G1>>>(
        x, pw1, fusion_b, bn1_gamma, bn1_beta, bn1_mean, bn1_var, x, pt1);
    // 5) deform (zero-offset) dwconv -> g_t2 (tf32-rounded for gemm2)
    dwconv_kernel<false, false, true><<<nplanes, 256>>>(pt1, deform_w, pt2,
                                                        nullptr, nullptr,
                                                        nullptr, nullptr);
    // 6) balance 1x1 conv + bias + BN2, gated by x -> out
    tgemm_kernel<256, false><<<grid, 256, SMEM_G2>>>(
        pt2, pw2, balance_b, bn2_gamma, bn2_beta, bn2_mean, bn2_var, x, out);
}